// round 2
// baseline (speedup 1.0000x reference)
#include <cuda_runtime.h>
#include <cuda_bf16.h>

// ---------------------------------------------------------------------------
// DynamicDWConv: fused pipeline
//   K1: per-(b,c) plane -> avgpool -> 3x dwconv5 (128^2) -> maxpool ->
//       3x dwconv5 (64^2) -> global mean  (all in shared memory)
//   K2: kern[b,o] = sum_c g[b,c]*wk[o,c] + bk[o]
//   K3: dynamic depthwise 5x5 conv on full-res x + bias
// ---------------------------------------------------------------------------

#define BATCH 8
#define CH    64
#define HW    256
#define BC    (BATCH * CH)       // 512
#define KK    25

// scratch (device globals; allocation in kernel_launch is forbidden)
__device__ float g_pool[BC];            // global-avg-pool result, [b*64+c]
__device__ float g_kern[BC * KK];       // dynamic kernels, [bc][25]

// ---------------- K1: plane pipeline ---------------------------------------
// smem layout (floats):
//   sA: 132*132  (stage-1 buffer, halo 2)
//   sB: 132*132
//   sC: 68*68    (stage-2 buffer, halo 2)
//   sD: 68*68
#define S1 132
#define S2 68
#define A_OFF 0
#define B_OFF (S1*S1)
#define C_OFF (2*S1*S1)
#define D_OFF (2*S1*S1 + S2*S2)
#define SMEM1_FLOATS (2*S1*S1 + 2*S2*S2)
#define NT1 512                   // K1 threads

// depthwise 5x5 conv, W x W plane with halo-2 buffers of row stride S.
// NT threads: tx = t % W column, group = t / W handles W/(NT/W) rows,
// y-blocked by 8 rows per iteration (column reload per dx tap).
template<int W, int S, int NT>
__device__ __forceinline__ void dwconv5(const float* __restrict__ src,
                                        float* __restrict__ dst,
                                        const float* __restrict__ wglob,
                                        float bias_v) {
    constexpr int NG  = NT / W;         // thread groups in y
    constexpr int RPG = W / NG;         // rows per group
    constexpr int NYB = RPG / 8;        // 8-row blocks per group
    const int t  = threadIdx.x;
    const int tx = t % W;
    const int g  = t / W;
    float w[KK];
#pragma unroll
    for (int i = 0; i < KK; i++) w[i] = wglob[i];

#pragma unroll
    for (int yb = 0; yb < NYB; yb++) {
        const int y0 = g * RPG + yb * 8;
        float acc[8];
#pragma unroll
        for (int i = 0; i < 8; i++) acc[i] = 0.f;
#pragma unroll
        for (int dx = 0; dx < 5; dx++) {
            float v[12];
#pragma unroll
            for (int r = 0; r < 12; r++)
                v[r] = src[(y0 + r) * S + tx + dx];
#pragma unroll
            for (int oy = 0; oy < 8; oy++)
#pragma unroll
                for (int dy = 0; dy < 5; dy++)
                    acc[oy] = fmaf(v[oy + dy], w[dy * 5 + dx], acc[oy]);
        }
#pragma unroll
        for (int oy = 0; oy < 8; oy++)
            dst[(y0 + oy + 2) * S + tx + 2] = acc[oy] + bias_v;
    }
}

__global__ __launch_bounds__(NT1, 1)
void k1_plane_pipeline(const float* __restrict__ x,
                       const float* __restrict__ w1,
                       const float* __restrict__ b1,
                       const float* __restrict__ w2,
                       const float* __restrict__ b2) {
    extern __shared__ float sm[];
    float* sA = sm + A_OFF;
    float* sB = sm + B_OFF;
    float* sC = sm + C_OFF;
    float* sD = sm + D_OFF;

    const int bc = blockIdx.x;            // 0..511
    const int c  = bc & (CH - 1);
    const int t  = threadIdx.x;
    const float* plane = x + (size_t)bc * HW * HW;

    // zero entire smem (halos must be zero; interiors get overwritten)
    for (int j = t; j < SMEM1_FLOATS; j += NT1) sm[j] = 0.f;
    __syncthreads();

    // avgpool 2x2: 256^2 -> 128^2 into sA interior (float2 vector loads)
    for (int i = t; i < 128 * 128; i += NT1) {
        const int oy = i >> 7, ox = i & 127;
        const float2* r0 = (const float2*)(plane + (2 * oy)     * HW);
        const float2* r1 = (const float2*)(plane + (2 * oy + 1) * HW);
        const float2 a = r0[ox], b = r1[ox];
        sA[(oy + 2) * S1 + ox + 2] = (a.x + a.y + b.x + b.y) * 0.25f;
    }
    __syncthreads();

    // block1: 3 depthwise convs on 128^2 (ping-pong A<->B)
    dwconv5<128, S1, NT1>(sA, sB, w1 + (0 * CH + c) * KK, b1[0 * CH + c]);
    __syncthreads();
    dwconv5<128, S1, NT1>(sB, sA, w1 + (1 * CH + c) * KK, b1[1 * CH + c]);
    __syncthreads();
    dwconv5<128, S1, NT1>(sA, sB, w1 + (2 * CH + c) * KK, b1[2 * CH + c]);
    __syncthreads();

    // maxpool 2x2: 128^2 -> 64^2 into sC interior
    for (int i = t; i < 64 * 64; i += NT1) {
        const int oy = i >> 6, ox = i & 63;
        const float* p = sB + (2 * oy + 2) * S1 + (2 * ox + 2);
        float m = fmaxf(fmaxf(p[0], p[1]), fmaxf(p[S1], p[S1 + 1]));
        sC[(oy + 2) * S2 + ox + 2] = m;
    }
    __syncthreads();

    // block2: 3 depthwise convs on 64^2 (ping-pong C<->D)
    dwconv5<64, S2, NT1>(sC, sD, w2 + (0 * CH + c) * KK, b2[0 * CH + c]);
    __syncthreads();
    dwconv5<64, S2, NT1>(sD, sC, w2 + (1 * CH + c) * KK, b2[1 * CH + c]);
    __syncthreads();
    dwconv5<64, S2, NT1>(sC, sD, w2 + (2 * CH + c) * KK, b2[2 * CH + c]);
    __syncthreads();

    // global mean of sD interior (64x64)
    float s = 0.f;
    for (int i = t; i < 64 * 64; i += NT1) {
        const int oy = i >> 6, ox = i & 63;
        s += sD[(oy + 2) * S2 + ox + 2];
    }
#pragma unroll
    for (int off = 16; off > 0; off >>= 1)
        s += __shfl_down_sync(0xffffffffu, s, off);
    if ((t & 31) == 0) sA[t >> 5] = s;   // sA free now; NT1/32 = 16 partials
    __syncthreads();
    if (t == 0) {
        float tot = 0.f;
#pragma unroll
        for (int wnum = 0; wnum < NT1 / 32; wnum++) tot += sA[wnum];
        g_pool[bc] = tot * (1.f / 4096.f);
    }
}

// ---------------- K2: kernel generation ------------------------------------
__global__ void k2_make_kernels(const float* __restrict__ wk,
                                const float* __restrict__ bk) {
    const int idx = blockIdx.x * blockDim.x + threadIdx.x;   // 0..12799
    if (idx >= BATCH * CH * KK) return;
    const int b = idx / (CH * KK);
    const int o = idx - b * (CH * KK);                        // 0..1599
    const float* gr = g_pool + b * CH;
    const float* wr = wk + (size_t)o * CH;
    float acc = bk[o];
#pragma unroll 8
    for (int c = 0; c < CH; c++) acc = fmaf(gr[c], wr[c], acc);
    g_kern[idx] = acc;   // idx = b*1600 + o = (b*64 + o/25)*25 + o%25 = bc*25+tap
}

// ---------------- K3: dynamic depthwise conv on full res -------------------
#define TH 32                 // tile rows
#define TS 260                // tile row stride (256 + 4 halo)
__global__ __launch_bounds__(256)
void k3_dyn_conv(const float* __restrict__ x,
                 const float* __restrict__ bias,
                 float* __restrict__ out) {
    __shared__ float tile[(TH + 4) * TS];    // 36 x 260 floats = 37.4 KB
    const int bc   = blockIdx.y;             // 0..511
    const int ch   = bc & (CH - 1);
    const int y0   = blockIdx.x * TH;        // 0..224
    const int t    = threadIdx.x;            // 0..255 (= output column)
    const float* plane = x + (size_t)bc * HW * HW;
    float*       po    = out + (size_t)bc * HW * HW;

    // load tile with halo (zero-pad outside image)
    for (int j = t; j < (TH + 4) * TS; j += 256) {
        const int r  = j / TS;
        const int cc = j - r * TS;
        const int gy = y0 - 2 + r;
        const int gx = cc - 2;
        float v = 0.f;
        if (gy >= 0 && gy < HW && gx >= 0 && gx < HW)
            v = plane[gy * HW + gx];
        tile[j] = v;
    }

    // per-plane dynamic 5x5 weights (uniform broadcast load)
    float w[KK];
    const float* kp = g_kern + bc * KK;
#pragma unroll
    for (int i = 0; i < KK; i++) w[i] = kp[i];
    const float bias_v = bias[ch];
    __syncthreads();

    // four 8-row blocks, y-blocked register scheme
#pragma unroll
    for (int yb = 0; yb < TH / 8; yb++) {
        float acc[8];
#pragma unroll
        for (int i = 0; i < 8; i++) acc[i] = 0.f;
#pragma unroll
        for (int dx = 0; dx < 5; dx++) {
            float v[12];
#pragma unroll
            for (int r = 0; r < 12; r++)
                v[r] = tile[(yb * 8 + r) * TS + t + dx];
#pragma unroll
            for (int oy = 0; oy < 8; oy++)
#pragma unroll
                for (int dy = 0; dy < 5; dy++)
                    acc[oy] = fmaf(v[oy + dy], w[dy * 5 + dx], acc[oy]);
        }
#pragma unroll
        for (int oy = 0; oy < 8; oy++)
            po[(y0 + yb * 8 + oy) * HW + t] = acc[oy] + bias_v;
    }
}

// ---------------- launch ----------------------------------------------------
extern "C" void kernel_launch(void* const* d_in, const int* in_sizes, int n_in,
                              void* d_out, int out_size) {
    const float* x    = (const float*)d_in[0];
    const float* w1   = (const float*)d_in[1];
    const float* b1   = (const float*)d_in[2];
    const float* w2   = (const float*)d_in[3];
    const float* b2   = (const float*)d_in[4];
    const float* wk   = (const float*)d_in[5];
    const float* bk   = (const float*)d_in[6];
    const float* bias = (const float*)d_in[7];
    float* out = (float*)d_out;

    // unconditional (idempotent, capture-safe): no static guards allowed
    cudaFuncSetAttribute(k1_plane_pipeline,
                         cudaFuncAttributeMaxDynamicSharedMemorySize,
                         SMEM1_FLOATS * (int)sizeof(float));

    k1_plane_pipeline<<<BC, NT1, SMEM1_FLOATS * sizeof(float)>>>(x, w1, b1, w2, b2);
    k2_make_kernels<<<(BATCH * CH * KK + 255) / 256, 256>>>(wk, bk);
    dim3 g3(HW / TH, BC);
    k3_dyn_conv<<<g3, 256>>>(x, bias, out);
}